// round 9
// baseline (speedup 1.0000x reference)
#include <cuda_runtime.h>
#include <cstdint>

// StructAttentionLayer: B=16384, A=50, D=256, fp32. HBM-bound (873MB, read once).
// R9 = R3/R8 skeleton (non-persistent, 1 tile/CTA, 52KB SMEM, 4 slots/SM) with
// a shorter per-tile tail:
//  (a) softmax REPLICATED in every warp -> weights live in registers; wsum
//      gets w[a] via __shfl_sync (ALU pipe) instead of SMEM broadcast loads.
//      Removes ~400 SMEM-port cyc/tile, one __syncthreads, and the
//      warp0-only serialization. ONE barrier per tile.
//  (b) 4-chunk TMA (13/13/13/11 rows): logits start when 13KB lands.

#define A_NUM 50
#define D_DIM 256
#define ALPHA 0.2f
#define TILE_BYTES (A_NUM * D_DIM * 4)     // 51200
#define ENT_BYTES  (D_DIM * 4)             // 1024
#define DYN_SMEM   (TILE_BYTES + ENT_BYTES)

__global__ __launch_bounds__(256, 4)
void struct_attn_kernel(const float* __restrict__ attrs,
                        const float* __restrict__ ent,
                        const float* __restrict__ aa,
                        float* __restrict__ out)
{
    extern __shared__ __align__(128) float sm[];
    float* tile = sm;                          // tile[a*256 + d], rows 0..49
    float* ents = sm + A_NUM * D_DIM;          // ents[256]

    __shared__ float e_s[52];                  // [0..49] logits, [50] entity dot
    __shared__ __align__(8) unsigned long long mbar[4];

    const int b    = blockIdx.x;
    const int t    = threadIdx.x;
    const int warp = t >> 5;
    const int lane = t & 31;

    uint32_t mba[4];
#pragma unroll
    for (int i = 0; i < 4; i++)
        mba[i] = (uint32_t)__cvta_generic_to_shared(&mbar[i]);
    const uint32_t tile_a = (uint32_t)__cvta_generic_to_shared(tile);

    // Chunk row layout: bases {0,13,26,39}, counts {13,13,13,11}. Chunk 0 also
    // carries the entity row.
    if (t == 0) {
#pragma unroll
        for (int i = 0; i < 4; i++)
            asm volatile("mbarrier.init.shared.b64 [%0], 1;" :: "r"(mba[i]) : "memory");
        asm volatile("fence.proxy.async.shared::cta;" ::: "memory");

        const float* gsrc = attrs + (size_t)b * (A_NUM * D_DIM);

        // chunk 0: rows 0..12 + entity row
        asm volatile("mbarrier.arrive.expect_tx.shared.b64 _, [%0], %1;"
                     :: "r"(mba[0]), "r"((uint32_t)(13 * 1024 + ENT_BYTES)) : "memory");
        asm volatile("cp.async.bulk.shared::cta.global.mbarrier::complete_tx::bytes "
                     "[%0], [%1], %2, [%3];"
                     :: "r"(tile_a), "l"(gsrc), "r"((uint32_t)(13 * 1024)), "r"(mba[0]) : "memory");
        asm volatile("cp.async.bulk.shared::cta.global.mbarrier::complete_tx::bytes "
                     "[%0], [%1], %2, [%3];"
                     :: "r"(tile_a + TILE_BYTES), "l"(ent + (size_t)b * D_DIM),
                        "r"((uint32_t)ENT_BYTES), "r"(mba[0]) : "memory");
        // chunks 1..3
        asm volatile("mbarrier.arrive.expect_tx.shared.b64 _, [%0], %1;"
                     :: "r"(mba[1]), "r"((uint32_t)(13 * 1024)) : "memory");
        asm volatile("cp.async.bulk.shared::cta.global.mbarrier::complete_tx::bytes "
                     "[%0], [%1], %2, [%3];"
                     :: "r"(tile_a + 13 * 1024), "l"(gsrc + 13 * D_DIM),
                        "r"((uint32_t)(13 * 1024)), "r"(mba[1]) : "memory");
        asm volatile("mbarrier.arrive.expect_tx.shared.b64 _, [%0], %1;"
                     :: "r"(mba[2]), "r"((uint32_t)(13 * 1024)) : "memory");
        asm volatile("cp.async.bulk.shared::cta.global.mbarrier::complete_tx::bytes "
                     "[%0], [%1], %2, [%3];"
                     :: "r"(tile_a + 26 * 1024), "l"(gsrc + 26 * D_DIM),
                        "r"((uint32_t)(13 * 1024)), "r"(mba[2]) : "memory");
        asm volatile("mbarrier.arrive.expect_tx.shared.b64 _, [%0], %1;"
                     :: "r"(mba[3]), "r"((uint32_t)(11 * 1024)) : "memory");
        asm volatile("cp.async.bulk.shared::cta.global.mbarrier::complete_tx::bytes "
                     "[%0], [%1], %2, [%3];"
                     :: "r"(tile_a + 39 * 1024), "l"(gsrc + 39 * D_DIM),
                        "r"((uint32_t)(11 * 1024)), "r"(mba[3]) : "memory");
    }

    // Weight vectors (2KB, L2-resident) — overlap TMA latency.
    const float4* aa4 = reinterpret_cast<const float4*>(aa);
    const float4 aw0 = aa4[lane];            // a_attr cols 4*lane..
    const float4 aw1 = aa4[32 + lane];       // a_attr cols 128+4*lane..

    __syncthreads();   // mbarrier inits visible before any try_wait

    const float4* tile4 = reinterpret_cast<const float4*>(tile);

#define WAIT_CHUNK(MB)                                                          \
    asm volatile(                                                               \
        "{\n\t.reg .pred P;\n\t"                                                \
        "WL%=:\n\t"                                                             \
        "mbarrier.try_wait.parity.acquire.cta.shared::cta.b64 P, [%0], 0, 0x989680;\n\t" \
        "@P bra WD%=;\n\tbra WL%=;\n\tWD%=:\n\t}" :: "r"(MB) : "memory")

#define ROW_LOGIT(a)                                                            \
    do {                                                                        \
        const float4 v0 = tile4[(a) * 64 + lane];                               \
        const float4 v1 = tile4[(a) * 64 + 32 + lane];                          \
        float s = v0.x * aw0.x + v0.y * aw0.y + v0.z * aw0.z + v0.w * aw0.w     \
                + v1.x * aw1.x + v1.y * aw1.y + v1.z * aw1.z + v1.w * aw1.w;    \
        s += __shfl_xor_sync(0xffffffffu, s, 16);                               \
        s += __shfl_xor_sync(0xffffffffu, s, 8);                                \
        s += __shfl_xor_sync(0xffffffffu, s, 4);                                \
        s += __shfl_xor_sync(0xffffffffu, s, 2);                                \
        s += __shfl_xor_sync(0xffffffffu, s, 1);                                \
        if (lane == 0) e_s[(a)] = s;                                            \
    } while (0)

    // chunk 0: rows 0..12 (+ entity dot on warp 7, which has only 1 row here)
    WAIT_CHUNK(mba[0]);
    ROW_LOGIT(warp);
    if (warp < 5) ROW_LOGIT(warp + 8);
    if (warp == 7) {
        const float4* e4 = reinterpret_cast<const float4*>(ents);
        const float4 ev0 = e4[lane];
        const float4 ev1 = e4[32 + lane];
        const float4 ew0 = aa4[64 + lane];   // a_ent
        const float4 ew1 = aa4[96 + lane];
        float pd = ev0.x * ew0.x + ev0.y * ew0.y + ev0.z * ew0.z + ev0.w * ew0.w
                 + ev1.x * ew1.x + ev1.y * ew1.y + ev1.z * ew1.z + ev1.w * ew1.w;
        pd += __shfl_xor_sync(0xffffffffu, pd, 16);
        pd += __shfl_xor_sync(0xffffffffu, pd, 8);
        pd += __shfl_xor_sync(0xffffffffu, pd, 4);
        pd += __shfl_xor_sync(0xffffffffu, pd, 2);
        pd += __shfl_xor_sync(0xffffffffu, pd, 1);
        if (lane == 0) e_s[A_NUM] = pd;
    }
    // chunk 1: rows 13..25
    WAIT_CHUNK(mba[1]);
    ROW_LOGIT(13 + warp);
    if (warp < 5) ROW_LOGIT(13 + warp + 8);
    // chunk 2: rows 26..38
    WAIT_CHUNK(mba[2]);
    ROW_LOGIT(26 + warp);
    if (warp < 5) ROW_LOGIT(26 + warp + 8);
    // chunk 3: rows 39..49
    WAIT_CHUNK(mba[3]);
    ROW_LOGIT(39 + warp);
    if (warp < 3) ROW_LOGIT(39 + warp + 8);

    __syncthreads();   // the ONLY per-tile barrier: e_s[0..50] complete

    // --- softmax over 50, REPLICATED in every warp (weights -> registers) ---
    const float ed = e_s[A_NUM];
    float x0 = e_s[lane] + ed;
    x0 = (x0 > 0.f) ? x0 : ALPHA * x0;
    float x1 = -1e30f;
    if (lane < A_NUM - 32) {
        x1 = e_s[lane + 32] + ed;
        x1 = (x1 > 0.f) ? x1 : ALPHA * x1;
    }
    float m = fmaxf(x0, x1);
    m = fmaxf(m, __shfl_xor_sync(0xffffffffu, m, 16));
    m = fmaxf(m, __shfl_xor_sync(0xffffffffu, m, 8));
    m = fmaxf(m, __shfl_xor_sync(0xffffffffu, m, 4));
    m = fmaxf(m, __shfl_xor_sync(0xffffffffu, m, 2));
    m = fmaxf(m, __shfl_xor_sync(0xffffffffu, m, 1));
    const float q0 = __expf(x0 - m);
    const float q1 = (lane < A_NUM - 32) ? __expf(x1 - m) : 0.f;
    float ssum = q0 + q1;
    ssum += __shfl_xor_sync(0xffffffffu, ssum, 16);
    ssum += __shfl_xor_sync(0xffffffffu, ssum, 8);
    ssum += __shfl_xor_sync(0xffffffffu, ssum, 4);
    ssum += __shfl_xor_sync(0xffffffffu, ssum, 2);
    ssum += __shfl_xor_sync(0xffffffffu, ssum, 1);
    const float inv = (float)A_NUM / ssum;
    const float w0 = q0 * inv;     // weight for row `lane`
    const float w1 = q1 * inv;     // weight for row `lane+32` (lane<18)

    // --- weighted sum: thread t owns output column t; w[a] via shuffle ---
    float acc0 = 0.f, acc1 = 0.f;
#pragma unroll
    for (int a = 0; a < 32; a += 2) {
        const float wa = __shfl_sync(0xffffffffu, w0, a);
        const float wb = __shfl_sync(0xffffffffu, w0, a + 1);
        acc0 = fmaf(wa, tile[a * D_DIM + t],       acc0);
        acc1 = fmaf(wb, tile[(a + 1) * D_DIM + t], acc1);
    }
#pragma unroll
    for (int a = 32; a < A_NUM; a += 2) {
        const float wa = __shfl_sync(0xffffffffu, w1, a - 32);
        const float wb = __shfl_sync(0xffffffffu, w1, a - 31);
        acc0 = fmaf(wa, tile[a * D_DIM + t],       acc0);
        acc1 = fmaf(wb, tile[(a + 1) * D_DIM + t], acc1);
    }
    __stcs(out + (size_t)b * D_DIM + t, acc0 + acc1);
#undef WAIT_CHUNK
#undef ROW_LOGIT
}

extern "C" void kernel_launch(void* const* d_in, const int* in_sizes, int n_in,
                              void* d_out, int out_size)
{
    const float* attrs = (const float*)d_in[0];   // [16384, 50, 256]
    const float* ent   = (const float*)d_in[1];   // [16384, 256]
    const float* aa    = (const float*)d_in[2];   // [512, 1]
    float* out         = (float*)d_out;           // [16384, 256]

    static int attr_set = 0;
    if (!attr_set) {
        cudaFuncSetAttribute(struct_attn_kernel,
                             cudaFuncAttributeMaxDynamicSharedMemorySize, DYN_SMEM);
        attr_set = 1;
    }

    const int B = in_sizes[1] / D_DIM;            // 16384
    struct_attn_kernel<<<B, 256, DYN_SMEM>>>(attrs, ent, aa, out);
}

// round 10
// speedup vs baseline: 1.0380x; 1.0380x over previous
#include <cuda_runtime.h>
#include <cstdint>

// StructAttentionLayer: B=16384, A=50, D=256, fp32. HBM-bound (873MB, read once).
// R10 = R8 (best: 127.5us, 85.6% DRAM — non-persistent, 1 tile/CTA, 52KB SMEM,
// 4 slots/SM, 2-chunk TMA, early issue, streaming out-stores) with ONE change:
// L2::evict_first cache policy on the bulk loads (attrs/ent are pure streaming,
// zero reuse — keep the dead lines from churning L2 / delaying writebacks).

#define A_NUM 50
#define D_DIM 256
#define ALPHA 0.2f
#define ROWS_A 24
#define CHUNKA_BYTES (ROWS_A * D_DIM * 4)               // 24576
#define CHUNKB_BYTES ((A_NUM - ROWS_A) * D_DIM * 4)     // 26624
#define ENT_BYTES    (D_DIM * 4)                        // 1024
#define TILE_BYTES   (A_NUM * D_DIM * 4)                // 51200
#define DYN_SMEM     (TILE_BYTES + ENT_BYTES)           // 52224

__global__ __launch_bounds__(256, 4)
void struct_attn_kernel(const float* __restrict__ attrs,
                        const float* __restrict__ ent,
                        const float* __restrict__ aa,
                        float* __restrict__ out)
{
    extern __shared__ __align__(128) float sm[];
    float* tile = sm;                          // tile[a*256 + d], rows 0..49
    float* ents = sm + A_NUM * D_DIM;          // ents[256]

    __shared__ float e_s[A_NUM + 2];
    __shared__ __align__(8) unsigned long long mbar[2];

    const int b    = blockIdx.x;
    const int t    = threadIdx.x;
    const int warp = t >> 5;
    const int lane = t & 31;

    const uint32_t mbA = (uint32_t)__cvta_generic_to_shared(&mbar[0]);
    const uint32_t mbB = (uint32_t)__cvta_generic_to_shared(&mbar[1]);
    const uint32_t tile_a = (uint32_t)__cvta_generic_to_shared(tile);

    // t0: init mbarriers and fire both chunk loads immediately (no barrier first).
    if (t == 0) {
        asm volatile("mbarrier.init.shared.b64 [%0], 1;" :: "r"(mbA) : "memory");
        asm volatile("mbarrier.init.shared.b64 [%0], 1;" :: "r"(mbB) : "memory");
        asm volatile("fence.proxy.async.shared::cta;" ::: "memory");

        unsigned long long pol;
        asm volatile("createpolicy.fractional.L2::evict_first.b64 %0, 1.0;" : "=l"(pol));

        const float* gsrc = attrs + (size_t)b * (A_NUM * D_DIM);
        // Chunk A: rows 0..23
        asm volatile("mbarrier.arrive.expect_tx.shared.b64 _, [%0], %1;"
                     :: "r"(mbA), "r"((uint32_t)CHUNKA_BYTES) : "memory");
        asm volatile("cp.async.bulk.shared::cta.global.mbarrier::complete_tx::bytes"
                     ".L2::cache_hint [%0], [%1], %2, [%3], %4;"
                     :: "r"(tile_a), "l"(gsrc),
                        "r"((uint32_t)CHUNKA_BYTES), "r"(mbA), "l"(pol) : "memory");
        // Chunk B: rows 24..49 + entity row
        asm volatile("mbarrier.arrive.expect_tx.shared.b64 _, [%0], %1;"
                     :: "r"(mbB), "r"((uint32_t)(CHUNKB_BYTES + ENT_BYTES)) : "memory");
        asm volatile("cp.async.bulk.shared::cta.global.mbarrier::complete_tx::bytes"
                     ".L2::cache_hint [%0], [%1], %2, [%3], %4;"
                     :: "r"(tile_a + CHUNKA_BYTES), "l"(gsrc + ROWS_A * D_DIM),
                        "r"((uint32_t)CHUNKB_BYTES), "r"(mbB), "l"(pol) : "memory");
        asm volatile("cp.async.bulk.shared::cta.global.mbarrier::complete_tx::bytes"
                     ".L2::cache_hint [%0], [%1], %2, [%3], %4;"
                     :: "r"(tile_a + TILE_BYTES), "l"(ent + (size_t)b * D_DIM),
                        "r"((uint32_t)ENT_BYTES), "r"(mbB), "l"(pol) : "memory");
    }

    // Weight vectors (2KB, L2-resident) — loads overlap TMA latency.
    const float4* aa4 = reinterpret_cast<const float4*>(aa);
    const float4 aw0 = aa4[lane];            // a_attr cols 4*lane..
    const float4 aw1 = aa4[32 + lane];       // a_attr cols 128+4*lane..

    __syncthreads();   // mbarrier inits visible before any try_wait

    const float4* tile4 = reinterpret_cast<const float4*>(tile);

    // --- wait chunk A; logits rows w, w+8, w+16 (all < 24) ---
    asm volatile(
        "{\n\t"
        ".reg .pred P;\n\t"
        "WLA%=:\n\t"
        "mbarrier.try_wait.parity.acquire.cta.shared::cta.b64 P, [%0], 0, 0x989680;\n\t"
        "@P bra WDA%=;\n\t"
        "bra WLA%=;\n\t"
        "WDA%=:\n\t"
        "}" :: "r"(mbA) : "memory");

#pragma unroll
    for (int i = 0; i < 3; i++) {
        const int a = warp + 8 * i;
        const float4 v0 = tile4[a * 64 + lane];
        const float4 v1 = tile4[a * 64 + 32 + lane];
        float s = v0.x * aw0.x + v0.y * aw0.y + v0.z * aw0.z + v0.w * aw0.w
                + v1.x * aw1.x + v1.y * aw1.y + v1.z * aw1.z + v1.w * aw1.w;
        s += __shfl_xor_sync(0xffffffffu, s, 16);
        s += __shfl_xor_sync(0xffffffffu, s, 8);
        s += __shfl_xor_sync(0xffffffffu, s, 4);
        s += __shfl_xor_sync(0xffffffffu, s, 2);
        s += __shfl_xor_sync(0xffffffffu, s, 1);
        if (lane == 0) e_s[a] = s;
    }

    // --- wait chunk B; logits rows w+24, w+32, w+40, w+48 (<50) + entity ---
    asm volatile(
        "{\n\t"
        ".reg .pred P;\n\t"
        "WLB%=:\n\t"
        "mbarrier.try_wait.parity.acquire.cta.shared::cta.b64 P, [%0], 0, 0x989680;\n\t"
        "@P bra WDB%=;\n\t"
        "bra WLB%=;\n\t"
        "WDB%=:\n\t"
        "}" :: "r"(mbB) : "memory");

#pragma unroll
    for (int i = 3; i < 7; i++) {
        const int a = warp + 8 * i;
        if (a < A_NUM) {
            const float4 v0 = tile4[a * 64 + lane];
            const float4 v1 = tile4[a * 64 + 32 + lane];
            float s = v0.x * aw0.x + v0.y * aw0.y + v0.z * aw0.z + v0.w * aw0.w
                    + v1.x * aw1.x + v1.y * aw1.y + v1.z * aw1.z + v1.w * aw1.w;
            s += __shfl_xor_sync(0xffffffffu, s, 16);
            s += __shfl_xor_sync(0xffffffffu, s, 8);
            s += __shfl_xor_sync(0xffffffffu, s, 4);
            s += __shfl_xor_sync(0xffffffffu, s, 2);
            s += __shfl_xor_sync(0xffffffffu, s, 1);
            if (lane == 0) e_s[a] = s;
        }
    }
    if (warp == 7) {
        const float4* e4 = reinterpret_cast<const float4*>(ents);
        const float4 ev0 = e4[lane];
        const float4 ev1 = e4[32 + lane];
        const float4 ew0 = aa4[64 + lane];   // a_ent
        const float4 ew1 = aa4[96 + lane];
        float pd = ev0.x * ew0.x + ev0.y * ew0.y + ev0.z * ew0.z + ev0.w * ew0.w
                 + ev1.x * ew1.x + ev1.y * ew1.y + ev1.z * ew1.z + ev1.w * ew1.w;
        pd += __shfl_xor_sync(0xffffffffu, pd, 16);
        pd += __shfl_xor_sync(0xffffffffu, pd, 8);
        pd += __shfl_xor_sync(0xffffffffu, pd, 4);
        pd += __shfl_xor_sync(0xffffffffu, pd, 2);
        pd += __shfl_xor_sync(0xffffffffu, pd, 1);
        if (lane == 0) e_s[A_NUM] = pd;
    }
    __syncthreads();

    // --- leaky-relu + softmax over 50 (warp 0), scaled by A_NUM ---
    if (warp == 0) {
        const float ed = e_s[A_NUM];
        float x0 = e_s[lane] + ed;
        x0 = (x0 > 0.f) ? x0 : ALPHA * x0;
        float x1 = -1e30f;
        if (lane < A_NUM - 32) {
            x1 = e_s[lane + 32] + ed;
            x1 = (x1 > 0.f) ? x1 : ALPHA * x1;
        }
        float m = fmaxf(x0, x1);
        m = fmaxf(m, __shfl_xor_sync(0xffffffffu, m, 16));
        m = fmaxf(m, __shfl_xor_sync(0xffffffffu, m, 8));
        m = fmaxf(m, __shfl_xor_sync(0xffffffffu, m, 4));
        m = fmaxf(m, __shfl_xor_sync(0xffffffffu, m, 2));
        m = fmaxf(m, __shfl_xor_sync(0xffffffffu, m, 1));
        const float q0 = __expf(x0 - m);
        const float q1 = (lane < A_NUM - 32) ? __expf(x1 - m) : 0.f;
        float ssum = q0 + q1;
        ssum += __shfl_xor_sync(0xffffffffu, ssum, 16);
        ssum += __shfl_xor_sync(0xffffffffu, ssum, 8);
        ssum += __shfl_xor_sync(0xffffffffu, ssum, 4);
        ssum += __shfl_xor_sync(0xffffffffu, ssum, 2);
        ssum += __shfl_xor_sync(0xffffffffu, ssum, 1);
        const float inv = (float)A_NUM / ssum;
        e_s[lane] = q0 * inv;
        if (lane < A_NUM - 32) e_s[lane + 32] = q1 * inv;
    }
    __syncthreads();

    // --- weighted sum: thread t owns output column t (conflict-free LDS) ---
    float a0 = 0.f, a1 = 0.f;
#pragma unroll
    for (int a = 0; a < A_NUM; a += 2) {
        a0 = fmaf(e_s[a],     tile[a * D_DIM + t],       a0);
        a1 = fmaf(e_s[a + 1], tile[(a + 1) * D_DIM + t], a1);
    }
    __stcs(out + (size_t)b * D_DIM + t, a0 + a1);   // streaming store
}

extern "C" void kernel_launch(void* const* d_in, const int* in_sizes, int n_in,
                              void* d_out, int out_size)
{
    const float* attrs = (const float*)d_in[0];   // [16384, 50, 256]
    const float* ent   = (const float*)d_in[1];   // [16384, 256]
    const float* aa    = (const float*)d_in[2];   // [512, 1]
    float* out         = (float*)d_out;           // [16384, 256]

    static int attr_set = 0;
    if (!attr_set) {
        cudaFuncSetAttribute(struct_attn_kernel,
                             cudaFuncAttributeMaxDynamicSharedMemorySize, DYN_SMEM);
        attr_set = 1;
    }

    const int B = in_sizes[1] / D_DIM;            // 16384
    struct_attn_kernel<<<B, 256, DYN_SMEM>>>(attrs, ent, aa, out);
}